// round 3
// baseline (speedup 1.0000x reference)
#include <cuda_runtime.h>
#include <stdint.h>

#define C 64
#define MAXN 100000

// Scratch for y = x @ W_neigh^T (device global: no allocs allowed in kernel_launch)
__device__ float g_ybuf[(size_t)MAXN * C];

// Packed dual-fp32 FMA (sm_100+): d = a*b + c elementwise on (lo,hi) pairs.
__device__ __forceinline__ unsigned long long ffma2(unsigned long long a,
                                                    unsigned long long b,
                                                    unsigned long long c) {
    unsigned long long d;
    asm("fma.rn.f32x2 %0, %1, %2, %3;" : "=l"(d) : "l"(a), "l"(b), "l"(c));
    return d;
}

__device__ __forceinline__ float hsum2(unsigned long long v) {
    unsigned lo, hi;
    asm("mov.b64 {%0, %1}, %2;" : "=r"(lo), "=r"(hi) : "l"(v));
    return __uint_as_float(lo) + __uint_as_float(hi);
}

// ---------------------------------------------------------------------------
// Kernel 1: per-node fused dual GEMM using packed f32x2 FMA.
//   out[n][:]  = x[n][:] @ Ws^T + (bs + bn)
//   ybuf[n][:] = x[n][:] @ Wn^T
// One thread per node; x row in 32 packed regs; W staged in shared
// (all lanes read the same W address per step -> broadcast LDS, conflict-free).
// fma.rn.f32x2 halves FMA instruction count vs scalar FFMA.
// ---------------------------------------------------------------------------
__global__ void __launch_bounds__(128)
fused_gemm_kernel(const float* __restrict__ x,
                  const float* __restrict__ Ws,
                  const float* __restrict__ bs,
                  const float* __restrict__ Wn,
                  const float* __restrict__ bn,
                  float* __restrict__ out,
                  int N) {
    __shared__ float sWs[C * C];
    __shared__ float sWn[C * C];
    __shared__ float sb[C];

    int tid = threadIdx.x;
    for (int i = tid; i < C * C; i += blockDim.x) {
        sWs[i] = Ws[i];
        sWn[i] = Wn[i];
    }
    if (tid < C) sb[tid] = bs[tid] + bn[tid];
    __syncthreads();

    int n = blockIdx.x * blockDim.x + tid;
    if (n >= N) return;

    // Load full x row as 8 x 16B = 16 packed f32x2 values (64 floats)
    ulonglong2 xr[8];
    const ulonglong2* xp = reinterpret_cast<const ulonglong2*>(x + (size_t)n * C);
#pragma unroll
    for (int i = 0; i < 8; i++) xr[i] = xp[i];

    float4* op = reinterpret_cast<float4*>(out + (size_t)n * C);
    float4* yp = reinterpret_cast<float4*>(g_ybuf + (size_t)n * C);

    // 4 output columns per iteration; outer loop rolled for I$ footprint.
#pragma unroll 1
    for (int jg = 0; jg < C; jg += 4) {
        unsigned long long accs[4], accn[4];
#pragma unroll
        for (int jj = 0; jj < 4; jj++) {
            // bias in lo half only
            accs[jj] = (unsigned long long)__float_as_uint(sb[jg + jj]);
            accn[jj] = 0ull;
        }
#pragma unroll
        for (int k4 = 0; k4 < 8; k4++) {
            ulonglong2 xv = xr[k4];  // pairs (x[8k..]): two f32x2 per 16B
            // each xr[k4] covers 4 floats? No: ulonglong2 = 16B = 4 floats =
            // 2 packed pairs. 8 iterations x 4 floats = 32... need 16 iters.
            // handled below via second half.
#pragma unroll
            for (int jj = 0; jj < 4; jj++) {
                const ulonglong2* wrow =
                    reinterpret_cast<const ulonglong2*>(&sWs[(jg + jj) * C]) + k4;
                ulonglong2 w = *wrow;
                accs[jj] = ffma2(xv.x, w.x, accs[jj]);
                accs[jj] = ffma2(xv.y, w.y, accs[jj]);
                const ulonglong2* urow =
                    reinterpret_cast<const ulonglong2*>(&sWn[(jg + jj) * C]) + k4;
                ulonglong2 u = *urow;
                accn[jj] = ffma2(xv.x, u.x, accn[jj]);
                accn[jj] = ffma2(xv.y, u.y, accn[jj]);
            }
        }
        // second half of k (floats 32..63)
#pragma unroll
        for (int k4 = 0; k4 < 0; k4++) {}  // (folded below)
        float4 os, oy;
        os.x = 0; // placeholder, real values set below
        // NOTE: loop above only covered k4 0..7 = floats 0..31. Do 8..15:
#pragma unroll
        for (int k4 = 8; k4 < 16; k4++) {
            ulonglong2 xv = ((const ulonglong2*)xr)[0]; // dummy; replaced below
            (void)xv;
        }
        // --- the above placeholder logic is unreachable; see fixed loop ---
        os.x = hsum2(accs[0]); os.y = hsum2(accs[1]);
        os.z = hsum2(accs[2]); os.w = hsum2(accs[3]);
        oy.x = hsum2(accn[0]); oy.y = hsum2(accn[1]);
        oy.z = hsum2(accn[2]); oy.w = hsum2(accn[3]);
        op[jg >> 2] = os;
        yp[jg >> 2] = oy;
    }
}

// The kernel above had a k-range bug risk; use this clean implementation
// instead (the one actually launched).
__global__ void __launch_bounds__(128)
fused_gemm_kernel2(const float* __restrict__ x,
                   const float* __restrict__ Ws,
                   const float* __restrict__ bs,
                   const float* __restrict__ Wn,
                   const float* __restrict__ bn,
                   float* __restrict__ out,
                   int N) {
    __shared__ float sWs[C * C];
    __shared__ float sWn[C * C];
    __shared__ float sb[C];

    int tid = threadIdx.x;
    for (int i = tid; i < C * C; i += blockDim.x) {
        sWs[i] = Ws[i];
        sWn[i] = Wn[i];
    }
    if (tid < C) sb[tid] = bs[tid] + bn[tid];
    __syncthreads();

    int n = blockIdx.x * blockDim.x + tid;
    if (n >= N) return;

    // x row: 16 x 16B vectors = 32 packed f32x2 (64 floats)
    ulonglong2 xr[16];
    const ulonglong2* xp = reinterpret_cast<const ulonglong2*>(x + (size_t)n * C);
#pragma unroll
    for (int i = 0; i < 16; i++) xr[i] = xp[i];
    // xr[i] holds floats [4i .. 4i+3]; .x = pair(4i,4i+1), .y = pair(4i+2,4i+3)
    // wait: 16 x 16B = 256B = 64 floats. C*4B = 256B. Correct.

    float4* op = reinterpret_cast<float4*>(out + (size_t)n * C);
    float4* yp = reinterpret_cast<float4*>(g_ybuf + (size_t)n * C);

#pragma unroll 1
    for (int jg = 0; jg < C; jg += 4) {
        unsigned long long accs[4], accn[4];
#pragma unroll
        for (int jj = 0; jj < 4; jj++) {
            accs[jj] = (unsigned long long)__float_as_uint(sb[jg + jj]);
            accn[jj] = 0ull;
        }
#pragma unroll
        for (int k4 = 0; k4 < 16; k4++) {
            ulonglong2 xv = xr[k4];
#pragma unroll
            for (int jj = 0; jj < 4; jj++) {
                ulonglong2 w = reinterpret_cast<const ulonglong2*>(
                                   &sWs[(jg + jj) * C])[k4];
                accs[jj] = ffma2(xv.x, w.x, accs[jj]);
                accs[jj] = ffma2(xv.y, w.y, accs[jj]);
                ulonglong2 u = reinterpret_cast<const ulonglong2*>(
                                   &sWn[(jg + jj) * C])[k4];
                accn[jj] = ffma2(xv.x, u.x, accn[jj]);
                accn[jj] = ffma2(xv.y, u.y, accn[jj]);
            }
        }
        float4 os, oy;
        os.x = hsum2(accs[0]); os.y = hsum2(accs[1]);
        os.z = hsum2(accs[2]); os.w = hsum2(accs[3]);
        oy.x = hsum2(accn[0]); oy.y = hsum2(accn[1]);
        oy.z = hsum2(accn[2]); oy.w = hsum2(accn[3]);
        op[jg >> 2] = os;
        yp[jg >> 2] = oy;
    }
}

// ---------------------------------------------------------------------------
// Kernel 2: edge scatter. 8 lanes per edge; lane i handles 32B (2 x float4).
//   out[row][:] += edge_weight * ybuf[col][:]
// edge_index is int32 on device (JAX x64 disabled downcasts int64).
// Halves the duplicated index loads vs 16 lanes/edge and gives 2 independent
// gather->RED chains per thread for ILP.
// ---------------------------------------------------------------------------
__global__ void __launch_bounds__(256)
scatter_kernel(const int* __restrict__ ei,
               const float* __restrict__ ew,
               float* __restrict__ out,
               int E) {
    long long t = (long long)blockIdx.x * blockDim.x + threadIdx.x;
    int e = (int)(t >> 3);
    if (e >= E) return;
    int lane = (int)t & 7;

    int dst = __ldg(ei + e);              // row (destination)
    int src = __ldg(ei + (size_t)E + e);  // col (source)
    float w = __ldg(ew + e);

    const float4* vp = reinterpret_cast<const float4*>(g_ybuf + (size_t)src * C)
                       + (lane << 1);
    float4 v0 = __ldg(vp);
    float4 v1 = __ldg(vp + 1);

    float4 r0 = make_float4(v0.x * w, v0.y * w, v0.z * w, v0.w * w);
    float4 r1 = make_float4(v1.x * w, v1.y * w, v1.z * w, v1.w * w);

    float* op = out + (size_t)dst * C + (lane << 3);
    asm volatile("red.global.add.v4.f32 [%0], {%1, %2, %3, %4};"
                 :: "l"(op), "f"(r0.x), "f"(r0.y), "f"(r0.z), "f"(r0.w)
                 : "memory");
    asm volatile("red.global.add.v4.f32 [%0], {%1, %2, %3, %4};"
                 :: "l"(op + 4), "f"(r1.x), "f"(r1.y), "f"(r1.z), "f"(r1.w)
                 : "memory");
}

// ---------------------------------------------------------------------------
// Inputs (metadata order): x[N*64] f32, edge_index[2*E] i32, edge_weight[E] f32,
// W_self[64*64] f32, b_self[64] f32, W_neigh[64*64] f32, b_neigh[64] f32,
// num_nodes (scalar, unused -- N derived from in_sizes[0]).
// Output: float32 [N*64].
// ---------------------------------------------------------------------------
extern "C" void kernel_launch(void* const* d_in, const int* in_sizes, int n_in,
                              void* d_out, int out_size) {
    const float* x  = (const float*)d_in[0];
    const int*   ei = (const int*)d_in[1];
    const float* ew = (const float*)d_in[2];
    const float* Ws = (const float*)d_in[3];
    const float* bs = (const float*)d_in[4];
    const float* Wn = (const float*)d_in[5];
    const float* bn = (const float*)d_in[6];
    float* out = (float*)d_out;

    int N = in_sizes[0] / C;
    int E = in_sizes[2];

    // 1) out = x@Ws^T + (bs+bn);  ybuf = x@Wn^T   (packed f32x2 FMA)
    fused_gemm_kernel2<<<(N + 127) / 128, 128>>>(x, Ws, bs, Wn, bn, out, N);

    // 2) out[row] += w * ybuf[col]   (vector atomics, 8 lanes/edge)
    long long total = (long long)E * 8;
    int blocks = (int)((total + 255) / 256);
    scatter_kernel<<<blocks, 256>>>(ei, ew, out, E);
}

// round 4
// speedup vs baseline: 1.3526x; 1.3526x over previous
#include <cuda_runtime.h>
#include <stdint.h>

#define C 64
#define MAXN 100000

// Scratch for y = x @ W_neigh^T (device global: no allocs allowed in kernel_launch)
__device__ float g_ybuf[(size_t)MAXN * C];

// ---------------------------------------------------------------------------
// Kernel 1: per-node fused dual GEMM (scalar FFMA — R2 known-good version).
//   out[n][:]  = x[n][:] @ Ws^T + (bs + bn)
//   ybuf[n][:] = x[n][:] @ Wn^T
// One thread per node; x row cached in 64 registers; W staged in shared
// (all lanes read the same W address per step -> broadcast LDS, conflict-free).
// ---------------------------------------------------------------------------
__global__ void __launch_bounds__(128)
fused_gemm_kernel(const float* __restrict__ x,
                  const float* __restrict__ Ws,
                  const float* __restrict__ bs,
                  const float* __restrict__ Wn,
                  const float* __restrict__ bn,
                  float* __restrict__ out,
                  int N) {
    __shared__ float sWs[C * C];
    __shared__ float sWn[C * C];
    __shared__ float sb[C];

    int tid = threadIdx.x;
    for (int i = tid; i < C * C; i += blockDim.x) {
        sWs[i] = Ws[i];
        sWn[i] = Wn[i];
    }
    if (tid < C) sb[tid] = bs[tid] + bn[tid];
    __syncthreads();

    int n = blockIdx.x * blockDim.x + tid;
    if (n >= N) return;

    // Load full x row into registers (16 x float4 = 64 floats)
    float4 xr[16];
    const float4* xp = reinterpret_cast<const float4*>(x + (size_t)n * C);
#pragma unroll
    for (int i = 0; i < 16; i++) xr[i] = xp[i];

    float4* op = reinterpret_cast<float4*>(out + (size_t)n * C);
    float4* yp = reinterpret_cast<float4*>(g_ybuf + (size_t)n * C);

    // 4 output columns per iteration; outer loop rolled for I$ footprint.
#pragma unroll 1
    for (int jg = 0; jg < C; jg += 4) {
        float accs[4], accn[4];
#pragma unroll
        for (int jj = 0; jj < 4; jj++) {
            accs[jj] = sb[jg + jj];
            accn[jj] = 0.0f;
        }
#pragma unroll
        for (int k = 0; k < 16; k++) {
            float4 xv = xr[k];
#pragma unroll
            for (int jj = 0; jj < 4; jj++) {
                float4 w = *reinterpret_cast<const float4*>(&sWs[(jg + jj) * C + k * 4]);
                accs[jj] = fmaf(xv.x, w.x, accs[jj]);
                accs[jj] = fmaf(xv.y, w.y, accs[jj]);
                accs[jj] = fmaf(xv.z, w.z, accs[jj]);
                accs[jj] = fmaf(xv.w, w.w, accs[jj]);
                float4 u = *reinterpret_cast<const float4*>(&sWn[(jg + jj) * C + k * 4]);
                accn[jj] = fmaf(xv.x, u.x, accn[jj]);
                accn[jj] = fmaf(xv.y, u.y, accn[jj]);
                accn[jj] = fmaf(xv.z, u.z, accn[jj]);
                accn[jj] = fmaf(xv.w, u.w, accn[jj]);
            }
        }
        op[jg >> 2] = make_float4(accs[0], accs[1], accs[2], accs[3]);
        yp[jg >> 2] = make_float4(accn[0], accn[1], accn[2], accn[3]);
    }
}

// ---------------------------------------------------------------------------
// Kernel 2: edge scatter. 16 lanes per edge (fully coalesced 256B row gather,
// R2 shape), but TWO independent edges per thread (e and e+H) to double
// memory-level parallelism — the R2 profile showed nothing saturated
// (L2 55%, issue 31%), i.e. latency-bound on idx->gather->RED chains.
//   out[row][:] += edge_weight * ybuf[col][:]
// edge_index is int32 on device (JAX x64 disabled downcasts int64).
// ---------------------------------------------------------------------------
__global__ void __launch_bounds__(256)
scatter_kernel(const int* __restrict__ ei,
               const float* __restrict__ ew,
               float* __restrict__ out,
               int E, int H) {
    long long t = (long long)blockIdx.x * blockDim.x + threadIdx.x;
    int e0 = (int)(t >> 4);
    if (e0 >= H) return;
    int lane = (int)t & 15;
    int e1 = e0 + H;
    bool has1 = (e1 < E);

    // Independent index/weight loads for both edges (issue all up front).
    int dst0 = __ldg(ei + e0);
    int src0 = __ldg(ei + (size_t)E + e0);
    float w0 = __ldg(ew + e0);
    int dst1 = 0, src1 = 0;
    float w1 = 0.0f;
    if (has1) {
        dst1 = __ldg(ei + e1);
        src1 = __ldg(ei + (size_t)E + e1);
        w1 = __ldg(ew + e1);
    }

    // Independent gathers (each warp: 2 coalesced 256B row reads per edge set).
    float4 v0 = __ldg(reinterpret_cast<const float4*>(g_ybuf + (size_t)src0 * C) + lane);
    float4 v1 = make_float4(0.f, 0.f, 0.f, 0.f);
    if (has1)
        v1 = __ldg(reinterpret_cast<const float4*>(g_ybuf + (size_t)src1 * C) + lane);

    float4 r0 = make_float4(v0.x * w0, v0.y * w0, v0.z * w0, v0.w * w0);
    float* op0 = out + (size_t)dst0 * C + (lane << 2);
    asm volatile("red.global.add.v4.f32 [%0], {%1, %2, %3, %4};"
                 :: "l"(op0), "f"(r0.x), "f"(r0.y), "f"(r0.z), "f"(r0.w)
                 : "memory");

    if (has1) {
        float4 r1 = make_float4(v1.x * w1, v1.y * w1, v1.z * w1, v1.w * w1);
        float* op1 = out + (size_t)dst1 * C + (lane << 2);
        asm volatile("red.global.add.v4.f32 [%0], {%1, %2, %3, %4};"
                     :: "l"(op1), "f"(r1.x), "f"(r1.y), "f"(r1.z), "f"(r1.w)
                     : "memory");
    }
}

// ---------------------------------------------------------------------------
// Inputs (metadata order): x[N*64] f32, edge_index[2*E] i32, edge_weight[E] f32,
// W_self[64*64] f32, b_self[64] f32, W_neigh[64*64] f32, b_neigh[64] f32,
// num_nodes (scalar, unused -- N derived from in_sizes[0]).
// Output: float32 [N*64].
// ---------------------------------------------------------------------------
extern "C" void kernel_launch(void* const* d_in, const int* in_sizes, int n_in,
                              void* d_out, int out_size) {
    const float* x  = (const float*)d_in[0];
    const int*   ei = (const int*)d_in[1];
    const float* ew = (const float*)d_in[2];
    const float* Ws = (const float*)d_in[3];
    const float* bs = (const float*)d_in[4];
    const float* Wn = (const float*)d_in[5];
    const float* bn = (const float*)d_in[6];
    float* out = (float*)d_out;

    int N = in_sizes[0] / C;
    int E = in_sizes[2];
    int H = (E + 1) / 2;

    // 1) out = x@Ws^T + (bs+bn);  ybuf = x@Wn^T
    fused_gemm_kernel<<<(N + 127) / 128, 128>>>(x, Ws, bs, Wn, bn, out, N);

    // 2) out[row] += w * ybuf[col]   (vector atomics, 2 edges/thread)
    long long total = (long long)H * 16;
    int blocks = (int)((total + 255) / 256);
    scatter_kernel<<<blocks, 256>>>(ei, ew, out, E, H);
}